// round 3
// baseline (speedup 1.0000x reference)
#include <cuda_runtime.h>
#include <cstdint>

#define N_NODES 50000
#define E_EDGES 800000

// ---------------- scratch (device globals; no allocation allowed) ----------
__device__ __align__(16) float4 g_agg1[N_NODES * 24];   // 96 floats / node (raw sums)
__device__ __align__(16) float4 g_agg2[N_NODES * 32];   // 128 floats / node (raw sums)
__device__ __align__(16) float4 g_h[N_NODES * 32];      // hidden activations, 128 / node
__device__ float    g_deg[N_NODES];
__device__ int      g_src[E_EDGES];
__device__ int      g_dst[E_EDGES];
__device__ int      g_is64;
__device__ unsigned g_b1l[128 * 3];   // sign bitmasks: bit=1 => weight>0
__device__ unsigned g_b1r[128 * 3];
__device__ unsigned g_b2l[64 * 4];
__device__ unsigned g_b2r[64 * 4];

// ---------------- helpers ---------------------------------------------------
__device__ __forceinline__ unsigned pack32(const float* p) {
    unsigned m = 0;
#pragma unroll
    for (int k = 0; k < 32; ++k)
        if (p[k] > 0.f) m |= (1u << k);
    return m;
}

// ---------------- kernels ---------------------------------------------------
// Detect whether the edge_index buffer is int64 or int32.
// For little-endian int64 values < 2^31, every odd 32-bit word is zero.
__global__ void k_detect(const int* __restrict__ ei32) {
    __shared__ int any_nonzero;
    if (threadIdx.x == 0) any_nonzero = 0;
    __syncthreads();
    int hi = ei32[2 * threadIdx.x + 1];
    if (hi != 0) atomicOr(&any_nonzero, 1);
    __syncthreads();
    if (threadIdx.x == 0) g_is64 = any_nonzero ? 0 : 1;
}

// Normalize indices to int32 (handles both dtypes).
__global__ void k_conv(const void* __restrict__ ei) {
    int e = blockIdx.x * blockDim.x + threadIdx.x;
    if (e >= E_EDGES) return;
    int s, d;
    if (g_is64) {
        const long long* p = (const long long*)ei;
        s = (int)p[e];
        d = (int)p[E_EDGES + e];
    } else {
        const int* p = (const int*)ei;
        s = p[e];
        d = p[E_EDGES + e];
    }
    g_src[e] = s;
    g_dst[e] = d;
    atomicAdd(&g_deg[d], 1.0f);   // fused degree count (no return -> RED)
}

__global__ void k_zero() {
    int i = blockIdx.x * blockDim.x + threadIdx.x;
    const float4 z = make_float4(0.f, 0.f, 0.f, 0.f);
    if (i < N_NODES * 24) g_agg1[i] = z;
    if (i < N_NODES * 32) g_agg2[i] = z;
    if (i < N_NODES)      g_deg[i] = 0.f;
}

__global__ void k_sign(const float* __restrict__ w1l, const float* __restrict__ w1r,
                       const float* __restrict__ w2l, const float* __restrict__ w2r) {
    int t = blockIdx.x * blockDim.x + threadIdx.x;
    if (t < 384) {                 // 128 rows * 3 words
        int r = t / 3, w = t - r * 3;
        g_b1l[t] = pack32(w1l + r * 96 + w * 32);
    } else if (t < 768) {
        int u = t - 384; int r = u / 3, w = u - r * 3;
        g_b1r[u] = pack32(w1r + r * 96 + w * 32);
    } else if (t < 1024) {         // 64 rows * 4 words
        int u = t - 768; int r = u >> 2, w = u & 3;
        g_b2l[u] = pack32(w2l + r * 128 + w * 32);
    } else if (t < 1280) {
        int u = t - 1024; int r = u >> 2, w = u & 3;
        g_b2r[u] = pack32(w2r + r * 128 + w * 32);
    }
}

// scatter-add: per (edge, float4 chunk) thread. LAYER=1: x -> agg1 ; LAYER=2: h -> agg2
template <int C, int LAYER>
__global__ void __launch_bounds__(256) k_scatter(const float4* __restrict__ xin) {
    int t = blockIdx.x * blockDim.x + threadIdx.x;
    if (t >= E_EDGES * C) return;
    int e = t / C;
    int c = t - e * C;
    int s = g_src[e];
    int d = g_dst[e];
    const float4* sf = (LAYER == 1) ? xin : (const float4*)g_h;
    float4*      agg = (LAYER == 1) ? g_agg1 : g_agg2;
    float4 v = sf[s * C + c];
    float* a = (float*)&agg[d * C + c];
    atomicAdd(a + 0, v.x);
    atomicAdd(a + 1, v.y);
    atomicAdd(a + 2, v.z);
    atomicAdd(a + 3, v.w);
}

// Binarized SAGE linear:  out = (2*sum_{bits_l} agg - sum agg)/deg + b + (2*sum_{bits_r} v - sum v)
template <int IN, int OUT, int NPB, bool RELU, int LAYER>
__global__ void __launch_bounds__(OUT) k_gemm(const float4* __restrict__ xin,
                                              const float* __restrict__ bias,
                                              float* __restrict__ outp) {
    constexpr int W  = IN / 32;
    constexpr int F4 = IN / 4;
    __shared__ float4 s_a4[NPB][F4];
    __shared__ float4 s_x4[NPB][F4];
    __shared__ float  s_inv[NPB];
    __shared__ float  s_Ta[NPB];
    __shared__ float  s_Tx[NPB];

    const float4*   vl     = (LAYER == 1) ? g_agg1 : g_agg2;
    const float4*   vr     = (LAYER == 1) ? xin    : (const float4*)g_h;
    const unsigned* bits_l = (LAYER == 1) ? g_b1l  : g_b2l;
    const unsigned* bits_r = (LAYER == 1) ? g_b1r  : g_b2r;
    float*          op     = (LAYER == 1) ? (float*)g_h : outp;

    const int o  = threadIdx.x;            // output column
    const int n0 = blockIdx.x * NPB;

    unsigned bl[W], br[W];
#pragma unroll
    for (int w = 0; w < W; ++w) {
        bl[w] = bits_l[o * W + w];
        br[w] = bits_r[o * W + w];
    }
    const float b = bias[o];

    // cooperative load of NPB node rows (both operands)
    for (int idx = o; idx < NPB * F4; idx += OUT) {
        int ni = idx / F4;
        int c  = idx - ni * F4;
        s_a4[ni][c] = vl[(size_t)(n0 + ni) * F4 + c];
        s_x4[ni][c] = vr[(size_t)(n0 + ni) * F4 + c];
    }
    if (o < NPB) {
        float dv = g_deg[n0 + o];
        s_inv[o] = 1.f / fmaxf(dv, 1.f);
    }
    __syncthreads();

    // per-node totals (for the 2*pos - total trick), one warp per node batch
    {
        int lane = o & 31, warp = o >> 5;
        for (int ni = warp; ni < NPB; ni += (OUT / 32)) {
            const float* va = (const float*)s_a4[ni];
            const float* vx = (const float*)s_x4[ni];
            float ta = 0.f, tx = 0.f;
#pragma unroll
            for (int f = lane; f < IN; f += 32) { ta += va[f]; tx += vx[f]; }
#pragma unroll
            for (int off = 16; off; off >>= 1) {
                ta += __shfl_xor_sync(0xffffffffu, ta, off);
                tx += __shfl_xor_sync(0xffffffffu, tx, off);
            }
            if (lane == 0) { s_Ta[ni] = ta; s_Tx[ni] = tx; }
        }
    }
    __syncthreads();

#pragma unroll 1
    for (int ni = 0; ni < NPB; ++ni) {
        const float* va = (const float*)s_a4[ni];
        const float* vx = (const float*)s_x4[ni];
        float a0 = 0.f, a1 = 0.f, r0 = 0.f, r1 = 0.f;
#pragma unroll
        for (int w = 0; w < W; ++w) {
            unsigned l = bl[w], r = br[w];
#pragma unroll
            for (int k = 0; k < 32; k += 2) {
                int f = w * 32 + k;
                float va0 = va[f], va1 = va[f + 1];
                float vx0 = vx[f], vx1 = vx[f + 1];
                if (l & (1u << k))      a0 += va0;   // predicated FADDs
                if (l & (2u << k))      a1 += va1;
                if (r & (1u << k))      r0 += vx0;
                if (r & (2u << k))      r1 += vx1;
            }
        }
        float accl = a0 + a1;
        float accr = r0 + r1;
        float res = (2.f * accl - s_Ta[ni]) * s_inv[ni] + b + (2.f * accr - s_Tx[ni]);
        if (RELU) res = fmaxf(res, 0.f);
        op[(size_t)(n0 + ni) * OUT + o] = res;
    }
}

// ---------------- launch ----------------------------------------------------
extern "C" void kernel_launch(void* const* d_in, const int* in_sizes, int n_in,
                              void* d_out, int out_size) {
    const float* x   = (const float*)d_in[0];
    const void*  ei  = d_in[1];
    const float* w1l = (const float*)d_in[2];
    const float* b1  = (const float*)d_in[3];
    const float* w1r = (const float*)d_in[4];
    const float* w2l = (const float*)d_in[5];
    const float* b2  = (const float*)d_in[6];
    const float* w2r = (const float*)d_in[7];
    float*       out = (float*)d_out;

    // 1. zero scratch (deg must be zero before k_conv's fused degree count)
    k_zero<<<(N_NODES * 32 + 255) / 256, 256>>>();
    // 2. detect edge dtype, convert indices to int32, count degrees
    k_detect<<<1, 256>>>((const int*)ei);
    k_conv<<<(E_EDGES + 255) / 256, 256>>>(ei);
    // 3. binarize weights into bitmasks
    k_sign<<<5, 256>>>(w1l, w1r, w2l, w2r);
    // 4. layer-1 scatter: agg1 += x[src]
    k_scatter<24, 1><<<(E_EDGES * 24 + 255) / 256, 256>>>((const float4*)x);
    // 5. layer-1 linear + relu -> h
    k_gemm<96, 128, 4, true, 1><<<N_NODES / 4, 128>>>((const float4*)x, b1, nullptr);
    // 6. layer-2 scatter: agg2 += h[src]
    k_scatter<32, 2><<<(E_EDGES * 32 + 255) / 256, 256>>>(nullptr);
    // 7. layer-2 linear -> out
    k_gemm<128, 64, 8, false, 2><<<N_NODES / 8, 64>>>(nullptr, b2, out);
}

// round 6
// speedup vs baseline: 3.3136x; 3.3136x over previous
#include <cuda_runtime.h>
#include <cstdint>

#define N_NODES 50000
#define E_EDGES 800000
#define NBLK 196            // ceil(50000/256)

// ---------------- scratch (device globals; no allocation allowed) ----------
__device__ __align__(16) float4 g_h[N_NODES * 32];   // hidden activations, 128/node
__device__ __align__(16) float  g_z[N_NODES * 64];   // layer-2 left transform
__device__ int g_degi[N_NODES];
__device__ int g_row[N_NODES];
__device__ int g_cur[N_NODES];
__device__ int g_src[E_EDGES];
__device__ int g_dst[E_EDGES];
__device__ int g_csr_src[E_EDGES];
__device__ int g_bsum[NBLK];
__device__ int g_bsumex[NBLK];
__device__ int g_is64;
__device__ unsigned g_b1l[128 * 3];   // sign bitmasks: bit=1 => weight>0
__device__ unsigned g_b1r[128 * 3];
__device__ unsigned g_b2l[64 * 4];
__device__ unsigned g_b2r[64 * 4];

// ---------------- helpers ---------------------------------------------------
__device__ __forceinline__ unsigned pack32(const float* p) {
    unsigned m = 0;
#pragma unroll
    for (int k = 0; k < 32; ++k)
        if (p[k] > 0.f) m |= (1u << k);
    return m;
}

// ---------------- index prep ------------------------------------------------
__global__ void k_zero_deg() {
    int i = blockIdx.x * blockDim.x + threadIdx.x;
    if (i < N_NODES) g_degi[i] = 0;
}

// int64 vs int32 detection: for LE int64 values < 2^31 every odd word is 0.
__global__ void k_detect(const int* __restrict__ ei32) {
    __shared__ int any_nonzero;
    if (threadIdx.x == 0) any_nonzero = 0;
    __syncthreads();
    if (ei32[2 * threadIdx.x + 1] != 0) atomicOr(&any_nonzero, 1);
    __syncthreads();
    if (threadIdx.x == 0) g_is64 = any_nonzero ? 0 : 1;
}

__global__ void k_conv(const void* __restrict__ ei) {
    int e = blockIdx.x * blockDim.x + threadIdx.x;
    if (e >= E_EDGES) return;
    int s, d;
    if (g_is64) {
        const long long* p = (const long long*)ei;
        s = (int)p[e];
        d = (int)p[E_EDGES + e];
    } else {
        const int* p = (const int*)ei;
        s = p[e];
        d = p[E_EDGES + e];
    }
    s = min(max(s, 0), N_NODES - 1);   // defensive clamp (never triggers on valid data)
    d = min(max(d, 0), N_NODES - 1);
    g_src[e] = s;
    g_dst[e] = d;
    atomicAdd(&g_degi[d], 1);
}

// 3-step exclusive scan of g_degi -> g_row
__global__ void k_scanA() {
    __shared__ int sh[256];
    int i = blockIdx.x * 256 + threadIdx.x;
    sh[threadIdx.x] = (i < N_NODES) ? g_degi[i] : 0;
    __syncthreads();
    for (int off = 128; off; off >>= 1) {
        if (threadIdx.x < off) sh[threadIdx.x] += sh[threadIdx.x + off];
        __syncthreads();
    }
    if (threadIdx.x == 0) g_bsum[blockIdx.x] = sh[0];
}
__global__ void k_scanB() {
    int acc = 0;
    for (int b = 0; b < NBLK; ++b) { g_bsumex[b] = acc; acc += g_bsum[b]; }
}
__global__ void k_scanC() {
    __shared__ int sh[256];
    int i = blockIdx.x * 256 + threadIdx.x;
    int v = (i < N_NODES) ? g_degi[i] : 0;
    sh[threadIdx.x] = v;
    __syncthreads();
    for (int off = 1; off < 256; off <<= 1) {
        int u = (threadIdx.x >= off) ? sh[threadIdx.x - off] : 0;
        __syncthreads();
        sh[threadIdx.x] += u;
        __syncthreads();
    }
    if (i < N_NODES) {
        int r = g_bsumex[blockIdx.x] + sh[threadIdx.x] - v;   // exclusive
        g_row[i] = r;
        g_cur[i] = r;
    }
}

__global__ void k_bucket() {
    int e = blockIdx.x * blockDim.x + threadIdx.x;
    if (e >= E_EDGES) return;
    int pos = atomicAdd(&g_cur[g_dst[e]], 1);
    pos = min(pos, E_EDGES - 1);       // defensive
    g_csr_src[pos] = g_src[e];
}

__global__ void k_sign(const float* __restrict__ w1l, const float* __restrict__ w1r,
                       const float* __restrict__ w2l, const float* __restrict__ w2r) {
    int t = blockIdx.x * blockDim.x + threadIdx.x;
    if (t < 384) {                 // 128 rows * 3 words
        int r = t / 3, w = t - r * 3;
        g_b1l[t] = pack32(w1l + r * 96 + w * 32);
    } else if (t < 768) {
        int u = t - 384; int r = u / 3, w = u - r * 3;
        g_b1r[u] = pack32(w1r + r * 96 + w * 32);
    } else if (t < 1024) {         // 64 rows * 4 words
        int u = t - 768; int r = u >> 2, w = u & 3;
        g_b2l[u] = pack32(w2l + r * 128 + w * 32);
    } else if (t < 1280) {
        int u = t - 1024; int r = u >> 2, w = u & 3;
        g_b2r[u] = pack32(w2r + r * 128 + w * 32);
    }
}

// ---------------- layer 1: fused gather-aggregate + binarized linear + relu --
// h[n] = relu( lin_l(mean_{j in N(n)} x[j]) + b1 + lin_r(x[n]) )
__global__ void __launch_bounds__(128) k_sage1(const float* __restrict__ x,
                                               const float* __restrict__ bias) {
    constexpr int IN = 96, OUT = 128, NPB = 4, W = 3, F4 = IN / 4;
    __shared__ float  s_a[NPB][IN];     // normalized neighbor mean
    __shared__ float4 s_x4[NPB][F4];    // own features
    __shared__ float  s_Ta[NPB], s_Tx[NPB];
    __shared__ int    s_start[NPB], s_deg[NPB];

    const int o  = threadIdx.x;
    const int n0 = blockIdx.x * NPB;

    if (o < NPB) {
        s_start[o] = g_row[n0 + o];
        s_deg[o]   = g_degi[n0 + o];
    }
    for (int idx = o; idx < NPB * F4; idx += OUT) {
        int ni = idx / F4, c = idx - ni * F4;
        s_x4[ni][c] = ((const float4*)x)[(size_t)(n0 + ni) * F4 + c];
    }
    __syncthreads();

    // gather-aggregate: 4 nodes x 96 feats = 384 units over 128 threads
    for (int u = o; u < NPB * IN; u += OUT) {
        int ni = u / IN, f = u - ni * IN;
        int st = s_start[ni], dg = s_deg[ni];
        float a0 = 0.f, a1 = 0.f, a2 = 0.f, a3 = 0.f;
        int j = 0;
        for (; j + 4 <= dg; j += 4) {
            int i0 = g_csr_src[st + j + 0];
            int i1 = g_csr_src[st + j + 1];
            int i2 = g_csr_src[st + j + 2];
            int i3 = g_csr_src[st + j + 3];
            a0 += x[(size_t)i0 * IN + f];
            a1 += x[(size_t)i1 * IN + f];
            a2 += x[(size_t)i2 * IN + f];
            a3 += x[(size_t)i3 * IN + f];
        }
        for (; j < dg; ++j) a0 += x[(size_t)g_csr_src[st + j] * IN + f];
        float inv = 1.f / fmaxf((float)dg, 1.f);
        s_a[ni][f] = (a0 + a1 + a2 + a3) * inv;
    }
    __syncthreads();

    // per-node row totals
    {
        int lane = o & 31, warp = o >> 5;
        for (int ni = warp; ni < NPB; ni += 4) {
            const float* va = s_a[ni];
            const float* vx = (const float*)s_x4[ni];
            float ta = 0.f, tx = 0.f;
#pragma unroll
            for (int f = lane; f < IN; f += 32) { ta += va[f]; tx += vx[f]; }
#pragma unroll
            for (int off = 16; off; off >>= 1) {
                ta += __shfl_xor_sync(0xffffffffu, ta, off);
                tx += __shfl_xor_sync(0xffffffffu, tx, off);
            }
            if (lane == 0) { s_Ta[ni] = ta; s_Tx[ni] = tx; }
        }
    }
    __syncthreads();

    unsigned bl[W], br[W];
#pragma unroll
    for (int w = 0; w < W; ++w) { bl[w] = g_b1l[o * W + w]; br[w] = g_b1r[o * W + w]; }
    const float b = bias[o];
    float* hp = (float*)g_h;

#pragma unroll 1
    for (int ni = 0; ni < NPB; ++ni) {
        const float* va = s_a[ni];
        const float* vx = (const float*)s_x4[ni];
        float a0 = 0.f, a1 = 0.f, r0 = 0.f, r1 = 0.f;
#pragma unroll
        for (int w = 0; w < W; ++w) {
            unsigned l = bl[w], r = br[w];
#pragma unroll
            for (int k = 0; k < 32; k += 2) {
                int f = w * 32 + k;
                float va0 = va[f], va1 = va[f + 1];
                float vx0 = vx[f], vx1 = vx[f + 1];
                if (l & (1u << k)) a0 += va0;
                if (l & (2u << k)) a1 += va1;
                if (r & (1u << k)) r0 += vx0;
                if (r & (2u << k)) r1 += vx1;
            }
        }
        float res = (2.f * (a0 + a1) - s_Ta[ni]) + b + (2.f * (r0 + r1) - s_Tx[ni]);
        res = fmaxf(res, 0.f);
        hp[(size_t)(n0 + ni) * OUT + o] = res;
    }
}

// ---------------- layer 2a: dual binarized transform of h --------------------
// z[n] = w2l_bin . h[n]  (unnormalized, aggregated later)
// out[n] = w2r_bin . h[n] + b2      (agg term added by k_agg2)
__global__ void __launch_bounds__(64) k_gemm2(const float* __restrict__ bias,
                                              float* __restrict__ outp) {
    constexpr int IN = 128, OUT = 64, NPB = 8, W = 4, F4 = IN / 4;
    __shared__ float4 s_h4[NPB][F4];
    __shared__ float  s_T[NPB];

    const int o  = threadIdx.x;
    const int n0 = blockIdx.x * NPB;

    for (int idx = o; idx < NPB * F4; idx += OUT) {
        int ni = idx / F4, c = idx - ni * F4;
        s_h4[ni][c] = g_h[(size_t)(n0 + ni) * F4 + c];
    }
    __syncthreads();
    {
        int lane = o & 31, warp = o >> 5;
        for (int ni = warp; ni < NPB; ni += 2) {
            const float* vh = (const float*)s_h4[ni];
            float t = 0.f;
#pragma unroll
            for (int f = lane; f < IN; f += 32) t += vh[f];
#pragma unroll
            for (int off = 16; off; off >>= 1) t += __shfl_xor_sync(0xffffffffu, t, off);
            if (lane == 0) s_T[ni] = t;
        }
    }
    __syncthreads();

    unsigned bl[W], br[W];
#pragma unroll
    for (int w = 0; w < W; ++w) { bl[w] = g_b2l[o * W + w]; br[w] = g_b2r[o * W + w]; }
    const float b = bias[o];

#pragma unroll 1
    for (int ni = 0; ni < NPB; ++ni) {
        const float* vh = (const float*)s_h4[ni];
        float a0 = 0.f, a1 = 0.f, r0 = 0.f, r1 = 0.f;
#pragma unroll
        for (int w = 0; w < W; ++w) {
            unsigned l = bl[w], r = br[w];
#pragma unroll
            for (int k = 0; k < 32; k += 2) {
                int f = w * 32 + k;
                float v0 = vh[f], v1 = vh[f + 1];
                if (l & (1u << k)) a0 += v0;
                if (l & (2u << k)) a1 += v1;
                if (r & (1u << k)) r0 += v0;
                if (r & (2u << k)) r1 += v1;
            }
        }
        float T = s_T[ni];
        g_z[(size_t)(n0 + ni) * OUT + o] = 2.f * (a0 + a1) - T;
        outp[(size_t)(n0 + ni) * OUT + o] = 2.f * (r0 + r1) - T + b;
    }
}

// ---------------- layer 2b: gather-aggregate z, finish output ----------------
__global__ void __launch_bounds__(256) k_agg2(float* __restrict__ outp) {
    constexpr int F = 64, NPB = 4;
    __shared__ int s_start[NPB], s_deg[NPB];
    const int t  = threadIdx.x;
    const int n0 = blockIdx.x * NPB;
    if (t < NPB) {
        s_start[t] = g_row[n0 + t];
        s_deg[t]   = g_degi[n0 + t];
    }
    __syncthreads();
    int ni = t >> 6, f = t & 63;          // 4 nodes x 64 feats = 256 units
    int st = s_start[ni], dg = s_deg[ni];
    float a0 = 0.f, a1 = 0.f, a2 = 0.f, a3 = 0.f;
    int j = 0;
    for (; j + 4 <= dg; j += 4) {
        int i0 = g_csr_src[st + j + 0];
        int i1 = g_csr_src[st + j + 1];
        int i2 = g_csr_src[st + j + 2];
        int i3 = g_csr_src[st + j + 3];
        a0 += g_z[(size_t)i0 * F + f];
        a1 += g_z[(size_t)i1 * F + f];
        a2 += g_z[(size_t)i2 * F + f];
        a3 += g_z[(size_t)i3 * F + f];
    }
    for (; j < dg; ++j) a0 += g_z[(size_t)g_csr_src[st + j] * F + f];
    float inv = 1.f / fmaxf((float)dg, 1.f);
    size_t oi = (size_t)(n0 + ni) * F + f;
    outp[oi] += (a0 + a1 + a2 + a3) * inv;
}

// ---------------- launch ----------------------------------------------------
extern "C" void kernel_launch(void* const* d_in, const int* in_sizes, int n_in,
                              void* d_out, int out_size) {
    const float* x   = (const float*)d_in[0];
    const void*  ei  = d_in[1];
    const float* w1l = (const float*)d_in[2];
    const float* b1  = (const float*)d_in[3];
    const float* w1r = (const float*)d_in[4];
    const float* w2l = (const float*)d_in[5];
    const float* b2  = (const float*)d_in[6];
    const float* w2r = (const float*)d_in[7];
    float*       out = (float*)d_out;

    k_zero_deg<<<NBLK, 256>>>();
    k_detect<<<1, 256>>>((const int*)ei);
    k_conv<<<(E_EDGES + 255) / 256, 256>>>(ei);
    k_scanA<<<NBLK, 256>>>();
    k_scanB<<<1, 1>>>();
    k_scanC<<<NBLK, 256>>>();
    k_bucket<<<(E_EDGES + 255) / 256, 256>>>();
    k_sign<<<5, 256>>>(w1l, w1r, w2l, w2r);
    k_sage1<<<N_NODES / 4, 128>>>(x, b1);
    k_gemm2<<<N_NODES / 8, 64>>>(b2, out);
    k_agg2<<<N_NODES / 4, 256>>>(out);
}

// round 7
// speedup vs baseline: 3.7974x; 1.1460x over previous
#include <cuda_runtime.h>
#include <cstdint>

#define N_NODES 50000
#define E_EDGES 800000
#define NBLK 196            // ceil(50000/256)

// ---------------- scratch (device globals; no allocation allowed) ----------
__device__ __align__(16) float4 g_h[N_NODES * 32];   // hidden activations, 128/node
__device__ __align__(16) float  g_z[N_NODES * 64];   // layer-2 left transform
__device__ int g_degi[N_NODES];
__device__ int g_row[N_NODES];
__device__ int g_cur[N_NODES];
__device__ int g_src[E_EDGES];
__device__ int g_dst[E_EDGES];
__device__ int g_csr_src[E_EDGES];
__device__ int g_bsum[NBLK];
__device__ int g_bsumex[NBLK];
__device__ int g_is64;
__device__ unsigned g_b1l[128 * 3];   // sign bitmasks: bit=1 => weight>0
__device__ unsigned g_b1r[128 * 3];
__device__ unsigned g_b2l[64 * 4];
__device__ unsigned g_b2r[64 * 4];

// ---------------- helpers ---------------------------------------------------
__device__ __forceinline__ unsigned pack32(const float* p) {
    unsigned m = 0;
#pragma unroll
    for (int k = 0; k < 32; ++k)
        if (p[k] > 0.f) m |= (1u << k);
    return m;
}

// acc += v via FFMA-imm (multiplier = 1.0 immediate -> rt_SMSP=1 path)
__device__ __forceinline__ void facc(float& acc, float v) {
    acc = __fmaf_rn(v, 1.0f, acc);
}

// ---------------- index prep ------------------------------------------------
__global__ void k_zero_deg() {
    int i = blockIdx.x * blockDim.x + threadIdx.x;
    if (i < N_NODES) g_degi[i] = 0;
}

// int64 vs int32 detection: for LE int64 values < 2^31 every odd word is 0.
__global__ void k_detect(const int* __restrict__ ei32) {
    __shared__ int any_nonzero;
    if (threadIdx.x == 0) any_nonzero = 0;
    __syncthreads();
    if (ei32[2 * threadIdx.x + 1] != 0) atomicOr(&any_nonzero, 1);
    __syncthreads();
    if (threadIdx.x == 0) g_is64 = any_nonzero ? 0 : 1;
}

__global__ void k_conv(const void* __restrict__ ei) {
    int e = blockIdx.x * blockDim.x + threadIdx.x;
    if (e >= E_EDGES) return;
    int s, d;
    if (g_is64) {
        const long long* p = (const long long*)ei;
        s = (int)p[e];
        d = (int)p[E_EDGES + e];
    } else {
        const int* p = (const int*)ei;
        s = p[e];
        d = p[E_EDGES + e];
    }
    s = min(max(s, 0), N_NODES - 1);   // defensive clamp
    d = min(max(d, 0), N_NODES - 1);
    g_src[e] = s;
    g_dst[e] = d;
    atomicAdd(&g_degi[d], 1);
}

// 3-step exclusive scan of g_degi -> g_row
__global__ void k_scanA() {
    __shared__ int sh[256];
    int i = blockIdx.x * 256 + threadIdx.x;
    sh[threadIdx.x] = (i < N_NODES) ? g_degi[i] : 0;
    __syncthreads();
    for (int off = 128; off; off >>= 1) {
        if (threadIdx.x < off) sh[threadIdx.x] += sh[threadIdx.x + off];
        __syncthreads();
    }
    if (threadIdx.x == 0) g_bsum[blockIdx.x] = sh[0];
}
__global__ void k_scanB() {
    int acc = 0;
    for (int b = 0; b < NBLK; ++b) { g_bsumex[b] = acc; acc += g_bsum[b]; }
}
__global__ void k_scanC() {
    __shared__ int sh[256];
    int i = blockIdx.x * 256 + threadIdx.x;
    int v = (i < N_NODES) ? g_degi[i] : 0;
    sh[threadIdx.x] = v;
    __syncthreads();
    for (int off = 1; off < 256; off <<= 1) {
        int u = (threadIdx.x >= off) ? sh[threadIdx.x - off] : 0;
        __syncthreads();
        sh[threadIdx.x] += u;
        __syncthreads();
    }
    if (i < N_NODES) {
        int r = g_bsumex[blockIdx.x] + sh[threadIdx.x] - v;   // exclusive
        g_row[i] = r;
        g_cur[i] = r;
    }
}

__global__ void k_bucket() {
    int e = blockIdx.x * blockDim.x + threadIdx.x;
    if (e >= E_EDGES) return;
    int pos = atomicAdd(&g_cur[g_dst[e]], 1);
    pos = min(pos, E_EDGES - 1);       // defensive
    g_csr_src[pos] = g_src[e];
}

__global__ void k_sign(const float* __restrict__ w1l, const float* __restrict__ w1r,
                       const float* __restrict__ w2l, const float* __restrict__ w2r) {
    int t = blockIdx.x * blockDim.x + threadIdx.x;
    if (t < 384) {                 // 128 rows * 3 words
        int r = t / 3, w = t - r * 3;
        g_b1l[t] = pack32(w1l + r * 96 + w * 32);
    } else if (t < 768) {
        int u = t - 384; int r = u / 3, w = u - r * 3;
        g_b1r[u] = pack32(w1r + r * 96 + w * 32);
    } else if (t < 1024) {         // 64 rows * 4 words
        int u = t - 768; int r = u >> 2, w = u & 3;
        g_b2l[u] = pack32(w2l + r * 128 + w * 32);
    } else if (t < 1280) {
        int u = t - 1024; int r = u >> 2, w = u & 3;
        g_b2r[u] = pack32(w2r + r * 128 + w * 32);
    }
}

// ---------------- layer 1: fused gather-aggregate + binarized linear + relu --
// h[n] = relu( lin_l(mean_{j in N(n)} x[j]) + b1 + lin_r(x[n]) )
__global__ void __launch_bounds__(128) k_sage1(const float* __restrict__ x,
                                               const float* __restrict__ bias) {
    constexpr int IN = 96, OUT = 128, NPB = 4, W = 3, F4 = IN / 4;
    __shared__ float4 s_a4[NPB][F4];    // normalized neighbor mean
    __shared__ float4 s_x4[NPB][F4];    // own features
    __shared__ float  s_Ta[NPB], s_Tx[NPB];
    __shared__ int    s_start[NPB], s_deg[NPB];

    const int o  = threadIdx.x;
    const int n0 = blockIdx.x * NPB;

    if (o < NPB) {
        s_start[o] = g_row[n0 + o];
        s_deg[o]   = g_degi[n0 + o];
    }
    for (int idx = o; idx < NPB * F4; idx += OUT) {
        int ni = idx / F4, c = idx - ni * F4;
        s_x4[ni][c] = ((const float4*)x)[(size_t)(n0 + ni) * F4 + c];
    }
    __syncthreads();

    // gather-aggregate: 4 nodes x 96 feats = 384 units over 128 threads
    for (int u = o; u < NPB * IN; u += OUT) {
        int ni = u / IN, f = u - ni * IN;
        int st = s_start[ni], dg = s_deg[ni];
        float a0 = 0.f, a1 = 0.f, a2 = 0.f, a3 = 0.f;
        int j = 0;
        for (; j + 4 <= dg; j += 4) {
            int i0 = g_csr_src[st + j + 0];
            int i1 = g_csr_src[st + j + 1];
            int i2 = g_csr_src[st + j + 2];
            int i3 = g_csr_src[st + j + 3];
            a0 += x[(size_t)i0 * IN + f];
            a1 += x[(size_t)i1 * IN + f];
            a2 += x[(size_t)i2 * IN + f];
            a3 += x[(size_t)i3 * IN + f];
        }
        for (; j < dg; ++j) a0 += x[(size_t)g_csr_src[st + j] * IN + f];
        float inv = 1.f / fmaxf((float)dg, 1.f);
        ((float*)s_a4[ni])[f] = (a0 + a1 + a2 + a3) * inv;
    }
    __syncthreads();

    // per-node row totals
    {
        int lane = o & 31, warp = o >> 5;
        for (int ni = warp; ni < NPB; ni += 4) {
            const float* va = (const float*)s_a4[ni];
            const float* vx = (const float*)s_x4[ni];
            float ta = 0.f, tx = 0.f;
#pragma unroll
            for (int f = lane; f < IN; f += 32) { ta += va[f]; tx += vx[f]; }
#pragma unroll
            for (int off = 16; off; off >>= 1) {
                ta += __shfl_xor_sync(0xffffffffu, ta, off);
                tx += __shfl_xor_sync(0xffffffffu, tx, off);
            }
            if (lane == 0) { s_Ta[ni] = ta; s_Tx[ni] = tx; }
        }
    }
    __syncthreads();

    unsigned bl[W], br[W];
#pragma unroll
    for (int w = 0; w < W; ++w) { bl[w] = g_b1l[o * W + w]; br[w] = g_b1r[o * W + w]; }
    const float b = bias[o];
    float* hp = (float*)g_h;

    // interchange: predicates per (w,k) hoisted over the node loop; FFMA-imm adds
    float La[NPB], Lb[NPB], Ra[NPB], Rb[NPB];
#pragma unroll
    for (int ni = 0; ni < NPB; ++ni) { La[ni] = Lb[ni] = Ra[ni] = Rb[ni] = 0.f; }

#pragma unroll
    for (int w = 0; w < W; ++w) {
        unsigned l = bl[w], r = br[w];
#pragma unroll
        for (int k = 0; k < 32; k += 4) {
            int c4 = (w * 32 + k) >> 2;
            {
                bool pl0 = (l >> k) & 1u, pl1 = (l >> (k + 1)) & 1u;
                bool pr0 = (r >> k) & 1u, pr1 = (r >> (k + 1)) & 1u;
#pragma unroll
                for (int ni = 0; ni < NPB; ++ni) {
                    float4 va = s_a4[ni][c4];
                    float4 vx = s_x4[ni][c4];
                    if (pl0) facc(La[ni], va.x);
                    if (pl1) facc(Lb[ni], va.y);
                    if (pr0) facc(Ra[ni], vx.x);
                    if (pr1) facc(Rb[ni], vx.y);
                }
            }
            {
                bool pl2 = (l >> (k + 2)) & 1u, pl3 = (l >> (k + 3)) & 1u;
                bool pr2 = (r >> (k + 2)) & 1u, pr3 = (r >> (k + 3)) & 1u;
#pragma unroll
                for (int ni = 0; ni < NPB; ++ni) {
                    float4 va = s_a4[ni][c4];
                    float4 vx = s_x4[ni][c4];
                    if (pl2) facc(La[ni], va.z);
                    if (pl3) facc(Lb[ni], va.w);
                    if (pr2) facc(Ra[ni], vx.z);
                    if (pr3) facc(Rb[ni], vx.w);
                }
            }
        }
    }

#pragma unroll
    for (int ni = 0; ni < NPB; ++ni) {
        float res = (2.f * (La[ni] + Lb[ni]) - s_Ta[ni]) + b
                  + (2.f * (Ra[ni] + Rb[ni]) - s_Tx[ni]);
        res = fmaxf(res, 0.f);
        hp[(size_t)(n0 + ni) * OUT + o] = res;
    }
}

// ---------------- layer 2a: dual binarized transform of h --------------------
// z[n] = w2l_bin . h[n]  (unnormalized, aggregated later)
// out[n] = w2r_bin . h[n] + b2      (agg term added by k_agg2)
__global__ void __launch_bounds__(64) k_gemm2(const float* __restrict__ bias,
                                              float* __restrict__ outp) {
    constexpr int IN = 128, OUT = 64, NPB = 8, W = 4, F4 = IN / 4;
    __shared__ float4 s_h4[NPB][F4];
    __shared__ float  s_T[NPB];

    const int o  = threadIdx.x;
    const int n0 = blockIdx.x * NPB;

    for (int idx = o; idx < NPB * F4; idx += OUT) {
        int ni = idx / F4, c = idx - ni * F4;
        s_h4[ni][c] = g_h[(size_t)(n0 + ni) * F4 + c];
    }
    __syncthreads();
    {
        int lane = o & 31, warp = o >> 5;
        for (int ni = warp; ni < NPB; ni += 2) {
            const float* vh = (const float*)s_h4[ni];
            float t = 0.f;
#pragma unroll
            for (int f = lane; f < IN; f += 32) t += vh[f];
#pragma unroll
            for (int off = 16; off; off >>= 1) t += __shfl_xor_sync(0xffffffffu, t, off);
            if (lane == 0) s_T[ni] = t;
        }
    }
    __syncthreads();

    unsigned bl[W], br[W];
#pragma unroll
    for (int w = 0; w < W; ++w) { bl[w] = g_b2l[o * W + w]; br[w] = g_b2r[o * W + w]; }
    const float b = bias[o];

    float La[NPB], Lb[NPB], Ra[NPB], Rb[NPB];
#pragma unroll
    for (int ni = 0; ni < NPB; ++ni) { La[ni] = Lb[ni] = Ra[ni] = Rb[ni] = 0.f; }

#pragma unroll
    for (int w = 0; w < W; ++w) {
        unsigned l = bl[w], r = br[w];
#pragma unroll
        for (int k = 0; k < 32; k += 4) {
            int c4 = (w * 32 + k) >> 2;
            {
                bool pl0 = (l >> k) & 1u, pl1 = (l >> (k + 1)) & 1u;
                bool pr0 = (r >> k) & 1u, pr1 = (r >> (k + 1)) & 1u;
#pragma unroll
                for (int ni = 0; ni < NPB; ++ni) {
                    float4 vh = s_h4[ni][c4];
                    if (pl0) facc(La[ni], vh.x);
                    if (pl1) facc(Lb[ni], vh.y);
                    if (pr0) facc(Ra[ni], vh.x);
                    if (pr1) facc(Rb[ni], vh.y);
                }
            }
            {
                bool pl2 = (l >> (k + 2)) & 1u, pl3 = (l >> (k + 3)) & 1u;
                bool pr2 = (r >> (k + 2)) & 1u, pr3 = (r >> (k + 3)) & 1u;
#pragma unroll
                for (int ni = 0; ni < NPB; ++ni) {
                    float4 vh = s_h4[ni][c4];
                    if (pl2) facc(La[ni], vh.z);
                    if (pl3) facc(Lb[ni], vh.w);
                    if (pr2) facc(Ra[ni], vh.z);
                    if (pr3) facc(Rb[ni], vh.w);
                }
            }
        }
    }

#pragma unroll
    for (int ni = 0; ni < NPB; ++ni) {
        float T = s_T[ni];
        g_z[(size_t)(n0 + ni) * OUT + o]   = 2.f * (La[ni] + Lb[ni]) - T;
        outp[(size_t)(n0 + ni) * OUT + o]  = 2.f * (Ra[ni] + Rb[ni]) - T + b;
    }
}

// ---------------- layer 2b: gather-aggregate z, finish output ----------------
__global__ void __launch_bounds__(256) k_agg2(float* __restrict__ outp) {
    constexpr int F = 64, NPB = 4;
    __shared__ int s_start[NPB], s_deg[NPB];
    const int t  = threadIdx.x;
    const int n0 = blockIdx.x * NPB;
    if (t < NPB) {
        s_start[t] = g_row[n0 + t];
        s_deg[t]   = g_degi[n0 + t];
    }
    __syncthreads();
    int ni = t >> 6, f = t & 63;          // 4 nodes x 64 feats = 256 units
    int st = s_start[ni], dg = s_deg[ni];
    float a0 = 0.f, a1 = 0.f, a2 = 0.f, a3 = 0.f;
    int j = 0;
    for (; j + 4 <= dg; j += 4) {
        int i0 = g_csr_src[st + j + 0];
        int i1 = g_csr_src[st + j + 1];
        int i2 = g_csr_src[st + j + 2];
        int i3 = g_csr_src[st + j + 3];
        a0 += g_z[(size_t)i0 * F + f];
        a1 += g_z[(size_t)i1 * F + f];
        a2 += g_z[(size_t)i2 * F + f];
        a3 += g_z[(size_t)i3 * F + f];
    }
    for (; j < dg; ++j) a0 += g_z[(size_t)g_csr_src[st + j] * F + f];
    float inv = 1.f / fmaxf((float)dg, 1.f);
    size_t oi = (size_t)(n0 + ni) * F + f;
    outp[oi] += (a0 + a1 + a2 + a3) * inv;
}

// ---------------- launch ----------------------------------------------------
extern "C" void kernel_launch(void* const* d_in, const int* in_sizes, int n_in,
                              void* d_out, int out_size) {
    const float* x   = (const float*)d_in[0];
    const void*  ei  = d_in[1];
    const float* w1l = (const float*)d_in[2];
    const float* b1  = (const float*)d_in[3];
    const float* w1r = (const float*)d_in[4];
    const float* w2l = (const float*)d_in[5];
    const float* b2  = (const float*)d_in[6];
    const float* w2r = (const float*)d_in[7];
    float*       out = (float*)d_out;

    k_zero_deg<<<NBLK, 256>>>();
    k_detect<<<1, 256>>>((const int*)ei);
    k_conv<<<(E_EDGES + 255) / 256, 256>>>(ei);
    k_scanA<<<NBLK, 256>>>();
    k_scanB<<<1, 1>>>();
    k_scanC<<<NBLK, 256>>>();
    k_bucket<<<(E_EDGES + 255) / 256, 256>>>();
    k_sign<<<5, 256>>>(w1l, w1r, w2l, w2r);
    k_sage1<<<N_NODES / 4, 128>>>(x, b1);
    k_gemm2<<<N_NODES / 8, 64>>>(b2, out);
    k_agg2<<<N_NODES / 4, 256>>>(out);
}

// round 10
// speedup vs baseline: 4.1698x; 1.0981x over previous
#include <cuda_runtime.h>
#include <cstdint>

#define N_NODES 50000
#define E_EDGES 800000
#define NBLK 196            // ceil(50000/256)

// ---------------- scratch (device globals; no allocation allowed) ----------
__device__ __align__(16) float g_z[N_NODES * 64];   // layer-2 left transform
__device__ int g_degi[N_NODES];
__device__ int g_row[N_NODES];
__device__ int g_cur[N_NODES];
__device__ int g_src[E_EDGES];
__device__ int g_dst[E_EDGES];
__device__ int g_csr_src[E_EDGES];
__device__ int g_bsum[NBLK];
__device__ int g_bsumex[NBLK];
__device__ int g_is64;
__device__ unsigned g_b1l[128 * 3];   // sign bitmasks: bit=1 => weight>0
__device__ unsigned g_b1r[128 * 3];
__device__ unsigned g_b2l[64 * 4];
__device__ unsigned g_b2r[64 * 4];

// acc += v via FFMA-imm (multiplier = 1.0 immediate -> rt_SMSP=1 path)
__device__ __forceinline__ void facc(float& acc, float v) {
    acc = __fmaf_rn(v, 1.0f, acc);
}

// ---------------- index prep ------------------------------------------------
__global__ void k_zero_deg() {
    int i = blockIdx.x * blockDim.x + threadIdx.x;
    if (i < N_NODES) g_degi[i] = 0;
}

// int64 vs int32 detection: for LE int64 values < 2^31 every odd word is 0.
__global__ void k_detect(const int* __restrict__ ei32) {
    __shared__ int any_nonzero;
    if (threadIdx.x == 0) any_nonzero = 0;
    __syncthreads();
    if (ei32[2 * threadIdx.x + 1] != 0) atomicOr(&any_nonzero, 1);
    __syncthreads();
    if (threadIdx.x == 0) g_is64 = any_nonzero ? 0 : 1;
}

// 2 edges per thread, vector loads
__global__ void k_conv(const void* __restrict__ ei) {
    int e = (blockIdx.x * blockDim.x + threadIdx.x) * 2;
    if (e >= E_EDGES) return;
    int s0, s1, d0, d1;
    if (g_is64) {
        const longlong2* ps = (const longlong2*)((const long long*)ei + e);
        const longlong2* pd = (const longlong2*)((const long long*)ei + E_EDGES + e);
        longlong2 vs = *ps, vd = *pd;
        s0 = (int)vs.x; s1 = (int)vs.y;
        d0 = (int)vd.x; d1 = (int)vd.y;
    } else {
        const int2* ps = (const int2*)((const int*)ei + e);
        const int2* pd = (const int2*)((const int*)ei + E_EDGES + e);
        int2 vs = *ps, vd = *pd;
        s0 = vs.x; s1 = vs.y;
        d0 = vd.x; d1 = vd.y;
    }
    s0 = min(max(s0, 0), N_NODES - 1);  s1 = min(max(s1, 0), N_NODES - 1);
    d0 = min(max(d0, 0), N_NODES - 1);  d1 = min(max(d1, 0), N_NODES - 1);
    *(int2*)&g_src[e] = make_int2(s0, s1);
    *(int2*)&g_dst[e] = make_int2(d0, d1);
    atomicAdd(&g_degi[d0], 1);
    atomicAdd(&g_degi[d1], 1);
}

// 3-step exclusive scan of g_degi -> g_row
__global__ void k_scanA() {
    __shared__ int sh[256];
    int i = blockIdx.x * 256 + threadIdx.x;
    sh[threadIdx.x] = (i < N_NODES) ? g_degi[i] : 0;
    __syncthreads();
    for (int off = 128; off; off >>= 1) {
        if (threadIdx.x < off) sh[threadIdx.x] += sh[threadIdx.x + off];
        __syncthreads();
    }
    if (threadIdx.x == 0) g_bsum[blockIdx.x] = sh[0];
}
__global__ void k_scanB() {      // parallel exclusive scan over NBLK<=256 sums
    __shared__ int sh[256];
    int t = threadIdx.x;
    int v = (t < NBLK) ? g_bsum[t] : 0;
    sh[t] = v;
    __syncthreads();
    for (int off = 1; off < 256; off <<= 1) {
        int u = (t >= off) ? sh[t - off] : 0;
        __syncthreads();
        sh[t] += u;
        __syncthreads();
    }
    if (t < NBLK) g_bsumex[t] = sh[t] - v;   // exclusive
}
__global__ void k_scanC() {
    __shared__ int sh[256];
    int i = blockIdx.x * 256 + threadIdx.x;
    int v = (i < N_NODES) ? g_degi[i] : 0;
    sh[threadIdx.x] = v;
    __syncthreads();
    for (int off = 1; off < 256; off <<= 1) {
        int u = (threadIdx.x >= off) ? sh[threadIdx.x - off] : 0;
        __syncthreads();
        sh[threadIdx.x] += u;
        __syncthreads();
    }
    if (i < N_NODES) {
        int r = g_bsumex[blockIdx.x] + sh[threadIdx.x] - v;   // exclusive
        g_row[i] = r;
        g_cur[i] = r;
    }
}

__global__ void k_bucket() {
    int e = blockIdx.x * blockDim.x + threadIdx.x;
    if (e >= E_EDGES) return;
    int pos = atomicAdd(&g_cur[g_dst[e]], 1);
    pos = min(pos, E_EDGES - 1);       // defensive
    g_csr_src[pos] = g_src[e];
}

// coalesced sign pack: one warp per 32-float chunk, ballot the signs.
// layouts are contiguous: w1l 384 words | w1r 384 | w2l 256 | w2r 256 = 1280 warps
__global__ void k_sign(const float* __restrict__ w1l, const float* __restrict__ w1r,
                       const float* __restrict__ w2l, const float* __restrict__ w2r) {
    int t    = blockIdx.x * blockDim.x + threadIdx.x;
    int gw   = t >> 5;
    int lane = t & 31;
    if (gw >= 1280) return;
    const float* src;
    unsigned* dst;
    int w;
    if (gw < 384)       { src = w1l; dst = g_b1l; w = gw; }
    else if (gw < 768)  { src = w1r; dst = g_b1r; w = gw - 384; }
    else if (gw < 1024) { src = w2l; dst = g_b2l; w = gw - 768; }
    else                { src = w2r; dst = g_b2r; w = gw - 1024; }
    unsigned m = __ballot_sync(0xffffffffu, src[w * 32 + lane] > 0.f);
    if (lane == 0) dst[w] = m;
}

// ---------------- fused layer1 + layer2 transform ----------------------------
// Per block (4 nodes):
//   h[n] = relu( lin_l1(mean x[N(n)]) + b1 + lin_r1(x[n]) )     (kept in smem)
//   z[n]   = w2l_bin . h[n]                                      -> g_z
//   out[n] = w2r_bin . h[n] + b2                                  -> outp
__global__ void __launch_bounds__(128) k_sage1(const float* __restrict__ x,
                                               const float* __restrict__ bias1,
                                               const float* __restrict__ bias2,
                                               float* __restrict__ outp) {
    constexpr int IN = 96, OUT = 128, NPB = 4, W = 3, F4 = IN / 4;
    __shared__ float4 s_a4[NPB][F4];    // normalized neighbor mean
    __shared__ float4 s_x4[NPB][F4];    // own features
    __shared__ float4 s_h4[NPB][OUT / 4];  // hidden activations (block-local)
    __shared__ float  s_Ta[NPB], s_Tx[NPB], s_Th[NPB];
    __shared__ int    s_start[NPB], s_deg[NPB];

    const int o  = threadIdx.x;
    const int n0 = blockIdx.x * NPB;

    if (o < NPB) {
        s_start[o] = g_row[n0 + o];
        s_deg[o]   = g_degi[n0 + o];
    }
    for (int idx = o; idx < NPB * F4; idx += OUT) {
        int ni = idx / F4, c = idx - ni * F4;
        s_x4[ni][c] = ((const float4*)x)[(size_t)(n0 + ni) * F4 + c];
    }
    __syncthreads();

    // gather-aggregate: 4 nodes x 96 feats = 384 units over 128 threads
    for (int u = o; u < NPB * IN; u += OUT) {
        int ni = u / IN, f = u - ni * IN;
        int st = s_start[ni], dg = s_deg[ni];
        float a0 = 0.f, a1 = 0.f, a2 = 0.f, a3 = 0.f;
        int j = 0;
        for (; j + 4 <= dg; j += 4) {
            int i0 = g_csr_src[st + j + 0];
            int i1 = g_csr_src[st + j + 1];
            int i2 = g_csr_src[st + j + 2];
            int i3 = g_csr_src[st + j + 3];
            a0 += x[(size_t)i0 * IN + f];
            a1 += x[(size_t)i1 * IN + f];
            a2 += x[(size_t)i2 * IN + f];
            a3 += x[(size_t)i3 * IN + f];
        }
        for (; j < dg; ++j) a0 += x[(size_t)g_csr_src[st + j] * IN + f];
        float inv = 1.f / fmaxf((float)dg, 1.f);
        ((float*)s_a4[ni])[f] = (a0 + a1 + a2 + a3) * inv;
    }
    __syncthreads();

    // per-node row totals of a and x
    {
        int lane = o & 31, warp = o >> 5;
        const float* va = (const float*)s_a4[warp];
        const float* vx = (const float*)s_x4[warp];
        float ta = 0.f, tx = 0.f;
#pragma unroll
        for (int f = lane; f < IN; f += 32) { ta += va[f]; tx += vx[f]; }
#pragma unroll
        for (int off = 16; off; off >>= 1) {
            ta += __shfl_xor_sync(0xffffffffu, ta, off);
            tx += __shfl_xor_sync(0xffffffffu, tx, off);
        }
        if (lane == 0) { s_Ta[warp] = ta; s_Tx[warp] = tx; }
    }
    __syncthreads();

    // ---- layer-1 binarized linear ----
    {
        unsigned bl[W], br[W];
#pragma unroll
        for (int w = 0; w < W; ++w) { bl[w] = g_b1l[o * W + w]; br[w] = g_b1r[o * W + w]; }
        const float b = bias1[o];

        float La[NPB], Lb[NPB], Ra[NPB], Rb[NPB];
#pragma unroll
        for (int ni = 0; ni < NPB; ++ni) { La[ni] = Lb[ni] = Ra[ni] = Rb[ni] = 0.f; }

#pragma unroll
        for (int w = 0; w < W; ++w) {
            unsigned l = bl[w], r = br[w];
#pragma unroll
            for (int k = 0; k < 32; k += 4) {
                int c4 = (w * 32 + k) >> 2;
                bool pl0 = (l >> k) & 1u, pl1 = (l >> (k + 1)) & 1u;
                bool pl2 = (l >> (k + 2)) & 1u, pl3 = (l >> (k + 3)) & 1u;
                bool pr0 = (r >> k) & 1u, pr1 = (r >> (k + 1)) & 1u;
                bool pr2 = (r >> (k + 2)) & 1u, pr3 = (r >> (k + 3)) & 1u;
#pragma unroll
                for (int ni = 0; ni < NPB; ++ni) {
                    float4 va = s_a4[ni][c4];
                    float4 vx = s_x4[ni][c4];
                    if (pl0) facc(La[ni], va.x);
                    if (pl1) facc(Lb[ni], va.y);
                    if (pl2) facc(La[ni], va.z);
                    if (pl3) facc(Lb[ni], va.w);
                    if (pr0) facc(Ra[ni], vx.x);
                    if (pr1) facc(Rb[ni], vx.y);
                    if (pr2) facc(Ra[ni], vx.z);
                    if (pr3) facc(Rb[ni], vx.w);
                }
            }
        }
#pragma unroll
        for (int ni = 0; ni < NPB; ++ni) {
            float res = (2.f * (La[ni] + Lb[ni]) - s_Ta[ni]) + b
                      + (2.f * (Ra[ni] + Rb[ni]) - s_Tx[ni]);
            ((float*)s_h4[ni])[o] = fmaxf(res, 0.f);
        }
    }
    __syncthreads();

    // per-node totals of h (warp ni reduces node ni)
    {
        int lane = o & 31, warp = o >> 5;
        const float* vh = (const float*)s_h4[warp];
        float t = 0.f;
#pragma unroll
        for (int f = lane; f < OUT; f += 32) t += vh[f];
#pragma unroll
        for (int off = 16; off; off >>= 1) t += __shfl_xor_sync(0xffffffffu, t, off);
        if (lane == 0) s_Th[warp] = t;
    }
    __syncthreads();

    // ---- layer-2 dual binarized transform (fused) ----
    // 128 threads = 2 groups x 64 output cols; group g handles nodes {2g, 2g+1}
    {
        constexpr int W2 = 4;
        const int grp = o >> 6;
        const int oc  = o & 63;
        unsigned bl[W2], br[W2];
#pragma unroll
        for (int w = 0; w < W2; ++w) { bl[w] = g_b2l[oc * W2 + w]; br[w] = g_b2r[oc * W2 + w]; }
        const float b = bias2[oc];

        float La[2], Lb[2], Ra[2], Rb[2];
#pragma unroll
        for (int q = 0; q < 2; ++q) { La[q] = Lb[q] = Ra[q] = Rb[q] = 0.f; }

#pragma unroll
        for (int w = 0; w < W2; ++w) {
            unsigned l = bl[w], r = br[w];
#pragma unroll
            for (int k = 0; k < 32; k += 4) {
                int c4 = (w * 32 + k) >> 2;
                bool pl0 = (l >> k) & 1u, pl1 = (l >> (k + 1)) & 1u;
                bool pl2 = (l >> (k + 2)) & 1u, pl3 = (l >> (k + 3)) & 1u;
                bool pr0 = (r >> k) & 1u, pr1 = (r >> (k + 1)) & 1u;
                bool pr2 = (r >> (k + 2)) & 1u, pr3 = (r >> (k + 3)) & 1u;
#pragma unroll
                for (int q = 0; q < 2; ++q) {
                    float4 vh = s_h4[2 * grp + q][c4];
                    if (pl0) facc(La[q], vh.x);
                    if (pl1) facc(Lb[q], vh.y);
                    if (pl2) facc(La[q], vh.z);
                    if (pl3) facc(Lb[q], vh.w);
                    if (pr0) facc(Ra[q], vh.x);
                    if (pr1) facc(Rb[q], vh.y);
                    if (pr2) facc(Ra[q], vh.z);
                    if (pr3) facc(Rb[q], vh.w);
                }
            }
        }
#pragma unroll
        for (int q = 0; q < 2; ++q) {
            int ni = 2 * grp + q;
            float T = s_Th[ni];
            g_z[(size_t)(n0 + ni) * 64 + oc]  = 2.f * (La[q] + Lb[q]) - T;
            outp[(size_t)(n0 + ni) * 64 + oc] = 2.f * (Ra[q] + Rb[q]) - T + b;
        }
    }
}

// ---------------- layer 2b: gather-aggregate z, finish output ----------------
__global__ void __launch_bounds__(256) k_agg2(float* __restrict__ outp) {
    constexpr int F = 64, NPB = 4;
    __shared__ int s_start[NPB], s_deg[NPB];
    const int t  = threadIdx.x;
    const int n0 = blockIdx.x * NPB;
    if (t < NPB) {
        s_start[t] = g_row[n0 + t];
        s_deg[t]   = g_degi[n0 + t];
    }
    __syncthreads();
    int ni = t >> 6, f = t & 63;          // 4 nodes x 64 feats = 256 units
    int st = s_start[ni], dg = s_deg[ni];
    float a0 = 0.f, a1 = 0.f, a2 = 0.f, a3 = 0.f;
    int j = 0;
    for (; j + 4 <= dg; j += 4) {
        int i0 = g_csr_src[st + j + 0];
        int i1 = g_csr_src[st + j + 1];
        int i2 = g_csr_src[st + j + 2];
        int i3 = g_csr_src[st + j + 3];
        a0 += g_z[(size_t)i0 * F + f];
        a1 += g_z[(size_t)i1 * F + f];
        a2 += g_z[(size_t)i2 * F + f];
        a3 += g_z[(size_t)i3 * F + f];
    }
    for (; j < dg; ++j) a0 += g_z[(size_t)g_csr_src[st + j] * F + f];
    float inv = 1.f / fmaxf((float)dg, 1.f);
    size_t oi = (size_t)(n0 + ni) * F + f;
    outp[oi] += (a0 + a1 + a2 + a3) * inv;
}

// ---------------- launch ----------------------------------------------------
extern "C" void kernel_launch(void* const* d_in, const int* in_sizes, int n_in,
                              void* d_out, int out_size) {
    const float* x   = (const float*)d_in[0];
    const void*  ei  = d_in[1];
    const float* w1l = (const float*)d_in[2];
    const float* b1  = (const float*)d_in[3];
    const float* w1r = (const float*)d_in[4];
    const float* w2l = (const float*)d_in[5];
    const float* b2  = (const float*)d_in[6];
    const float* w2r = (const float*)d_in[7];
    float*       out = (float*)d_out;

    k_zero_deg<<<NBLK, 256>>>();
    k_detect<<<1, 256>>>((const int*)ei);
    k_conv<<<(E_EDGES / 2 + 255) / 256, 256>>>(ei);
    k_scanA<<<NBLK, 256>>>();
    k_scanB<<<1, 256>>>();
    k_scanC<<<NBLK, 256>>>();
    k_bucket<<<(E_EDGES + 255) / 256, 256>>>();
    k_sign<<<160, 256>>>(w1l, w1r, w2l, w2r);
    k_sage1<<<N_NODES / 4, 128>>>(x, b1, b2, out);
    k_agg2<<<N_NODES / 4, 256>>>(out);
}

// round 11
// speedup vs baseline: 4.7427x; 1.1374x over previous
#include <cuda_runtime.h>
#include <cstdint>

#define N_NODES 50000
#define E_EDGES 800000
#define NBLK 196            // ceil(50000/256)

// ---------------- scratch (device globals; no allocation allowed) ----------
__device__ __align__(16) float g_z[N_NODES * 64];   // layer-2 left transform
__device__ int g_degi[N_NODES];
__device__ int g_row[N_NODES];
__device__ int g_cur[N_NODES];
__device__ int g_src[E_EDGES];
__device__ int g_dst[E_EDGES];
__device__ int g_csr_src[E_EDGES];
__device__ int g_bsum[NBLK];
__device__ int g_bsumex[NBLK];
__device__ int g_is64;
__device__ unsigned g_b1l[128 * 3];   // sign bitmasks: bit=1 => weight>0
__device__ unsigned g_b1r[128 * 3];
__device__ unsigned g_b2l[64 * 4];
__device__ unsigned g_b2r[64 * 4];

// acc += v via FFMA-imm (multiplier = 1.0 immediate -> rt_SMSP=1 path)
__device__ __forceinline__ void facc(float& acc, float v) {
    acc = __fmaf_rn(v, 1.0f, acc);
}

// ---------------- fused init: zero degrees + dtype detect + sign pack -------
__global__ void k_init(const int* __restrict__ ei32,
                       const float* __restrict__ w1l, const float* __restrict__ w1r,
                       const float* __restrict__ w2l, const float* __restrict__ w2r) {
    int t = blockIdx.x * blockDim.x + threadIdx.x;
    if (t < N_NODES) g_degi[t] = 0;

    // dtype detect (block 0 only): LE int64 < 2^31 has zero odd words
    if (blockIdx.x == 0) {
        __shared__ int any_nonzero;
        if (threadIdx.x == 0) any_nonzero = 0;
        __syncthreads();
        if (ei32[2 * threadIdx.x + 1] != 0) atomicOr(&any_nonzero, 1);
        __syncthreads();
        if (threadIdx.x == 0) g_is64 = any_nonzero ? 0 : 1;
    }

    // sign pack: one warp per 32-float chunk; 1280 warps total
    int gw   = t >> 5;
    int lane = t & 31;
    if (gw < 1280) {
        const float* src;
        unsigned* dst;
        int w;
        if (gw < 384)       { src = w1l; dst = g_b1l; w = gw; }
        else if (gw < 768)  { src = w1r; dst = g_b1r; w = gw - 384; }
        else if (gw < 1024) { src = w2l; dst = g_b2l; w = gw - 768; }
        else                { src = w2r; dst = g_b2r; w = gw - 1024; }
        unsigned m = __ballot_sync(0xffffffffu, src[w * 32 + lane] > 0.f);
        if (lane == 0) dst[w] = m;
    }
}

// 2 edges per thread, vector loads
__global__ void k_conv(const void* __restrict__ ei) {
    int e = (blockIdx.x * blockDim.x + threadIdx.x) * 2;
    if (e >= E_EDGES) return;
    int s0, s1, d0, d1;
    if (g_is64) {
        const longlong2* ps = (const longlong2*)((const long long*)ei + e);
        const longlong2* pd = (const longlong2*)((const long long*)ei + E_EDGES + e);
        longlong2 vs = *ps, vd = *pd;
        s0 = (int)vs.x; s1 = (int)vs.y;
        d0 = (int)vd.x; d1 = (int)vd.y;
    } else {
        const int2* ps = (const int2*)((const int*)ei + e);
        const int2* pd = (const int2*)((const int*)ei + E_EDGES + e);
        int2 vs = *ps, vd = *pd;
        s0 = vs.x; s1 = vs.y;
        d0 = vd.x; d1 = vd.y;
    }
    s0 = min(max(s0, 0), N_NODES - 1);  s1 = min(max(s1, 0), N_NODES - 1);
    d0 = min(max(d0, 0), N_NODES - 1);  d1 = min(max(d1, 0), N_NODES - 1);
    *(int2*)&g_src[e] = make_int2(s0, s1);
    *(int2*)&g_dst[e] = make_int2(d0, d1);
    atomicAdd(&g_degi[d0], 1);
    atomicAdd(&g_degi[d1], 1);
}

// 3-step exclusive scan of g_degi -> g_row
__global__ void k_scanA() {
    __shared__ int sh[256];
    int i = blockIdx.x * 256 + threadIdx.x;
    sh[threadIdx.x] = (i < N_NODES) ? g_degi[i] : 0;
    __syncthreads();
    for (int off = 128; off; off >>= 1) {
        if (threadIdx.x < off) sh[threadIdx.x] += sh[threadIdx.x + off];
        __syncthreads();
    }
    if (threadIdx.x == 0) g_bsum[blockIdx.x] = sh[0];
}
__global__ void k_scanB() {      // parallel exclusive scan over NBLK<=256 sums
    __shared__ int sh[256];
    int t = threadIdx.x;
    int v = (t < NBLK) ? g_bsum[t] : 0;
    sh[t] = v;
    __syncthreads();
    for (int off = 1; off < 256; off <<= 1) {
        int u = (t >= off) ? sh[t - off] : 0;
        __syncthreads();
        sh[t] += u;
        __syncthreads();
    }
    if (t < NBLK) g_bsumex[t] = sh[t] - v;   // exclusive
}
__global__ void k_scanC() {
    __shared__ int sh[256];
    int i = blockIdx.x * 256 + threadIdx.x;
    int v = (i < N_NODES) ? g_degi[i] : 0;
    sh[threadIdx.x] = v;
    __syncthreads();
    for (int off = 1; off < 256; off <<= 1) {
        int u = (threadIdx.x >= off) ? sh[threadIdx.x - off] : 0;
        __syncthreads();
        sh[threadIdx.x] += u;
        __syncthreads();
    }
    if (i < N_NODES) {
        int r = g_bsumex[blockIdx.x] + sh[threadIdx.x] - v;   // exclusive
        g_row[i] = r;
        g_cur[i] = r;
    }
}

__global__ void k_bucket() {
    int e = blockIdx.x * blockDim.x + threadIdx.x;
    if (e >= E_EDGES) return;
    int pos = atomicAdd(&g_cur[g_dst[e]], 1);
    pos = min(pos, E_EDGES - 1);       // defensive
    g_csr_src[pos] = g_src[e];
}

// ---------------- fused layer1 + layer2 transform ----------------------------
__global__ void __launch_bounds__(128) k_sage1(const float* __restrict__ x,
                                               const float* __restrict__ bias1,
                                               const float* __restrict__ bias2,
                                               float* __restrict__ outp) {
    constexpr int IN = 96, OUT = 128, NPB = 4, W = 3, F4 = IN / 4;
    __shared__ float4 s_a4[NPB][F4];    // normalized neighbor mean
    __shared__ float4 s_x4[NPB][F4];    // own features
    __shared__ float4 s_h4[NPB][OUT / 4];  // hidden activations (block-local)
    __shared__ float  s_Ta[NPB], s_Tx[NPB], s_Th[NPB];
    __shared__ int    s_start[NPB], s_deg[NPB];

    const int o  = threadIdx.x;
    const int n0 = blockIdx.x * NPB;

    if (o < NPB) {
        s_start[o] = g_row[n0 + o];
        s_deg[o]   = g_degi[n0 + o];
    }
    for (int idx = o; idx < NPB * F4; idx += OUT) {
        int ni = idx / F4, c = idx - ni * F4;
        s_x4[ni][c] = ((const float4*)x)[(size_t)(n0 + ni) * F4 + c];
    }
    __syncthreads();

    // float4 gather-aggregate: thread -> (node, float4 chunk); 96 active lanes
    if (o < NPB * F4) {
        int ni = o / F4, c4 = o - ni * F4;
        int st = s_start[ni], dg = s_deg[ni];
        const float4* x4 = (const float4*)x;
        float4 a0 = make_float4(0.f, 0.f, 0.f, 0.f);
        float4 a1 = a0, a2 = a0, a3 = a0;
        int j = 0;
        for (; j + 4 <= dg; j += 4) {
            int i0 = g_csr_src[st + j + 0];
            int i1 = g_csr_src[st + j + 1];
            int i2 = g_csr_src[st + j + 2];
            int i3 = g_csr_src[st + j + 3];
            float4 v0 = x4[(size_t)i0 * F4 + c4];
            float4 v1 = x4[(size_t)i1 * F4 + c4];
            float4 v2 = x4[(size_t)i2 * F4 + c4];
            float4 v3 = x4[(size_t)i3 * F4 + c4];
            a0.x += v0.x; a0.y += v0.y; a0.z += v0.z; a0.w += v0.w;
            a1.x += v1.x; a1.y += v1.y; a1.z += v1.z; a1.w += v1.w;
            a2.x += v2.x; a2.y += v2.y; a2.z += v2.z; a2.w += v2.w;
            a3.x += v3.x; a3.y += v3.y; a3.z += v3.z; a3.w += v3.w;
        }
        for (; j < dg; ++j) {
            float4 v = x4[(size_t)g_csr_src[st + j] * F4 + c4];
            a0.x += v.x; a0.y += v.y; a0.z += v.z; a0.w += v.w;
        }
        float inv = 1.f / fmaxf((float)dg, 1.f);
        float4 res;
        res.x = (a0.x + a1.x + a2.x + a3.x) * inv;
        res.y = (a0.y + a1.y + a2.y + a3.y) * inv;
        res.z = (a0.z + a1.z + a2.z + a3.z) * inv;
        res.w = (a0.w + a1.w + a2.w + a3.w) * inv;
        s_a4[ni][c4] = res;
    }
    __syncthreads();

    // per-node row totals of a and x (warp ni reduces node ni)
    {
        int lane = o & 31, warp = o >> 5;
        const float* va = (const float*)s_a4[warp];
        const float* vx = (const float*)s_x4[warp];
        float ta = 0.f, tx = 0.f;
#pragma unroll
        for (int f = lane; f < IN; f += 32) { ta += va[f]; tx += vx[f]; }
#pragma unroll
        for (int off = 16; off; off >>= 1) {
            ta += __shfl_xor_sync(0xffffffffu, ta, off);
            tx += __shfl_xor_sync(0xffffffffu, tx, off);
        }
        if (lane == 0) { s_Ta[warp] = ta; s_Tx[warp] = tx; }
    }
    __syncthreads();

    // ---- layer-1 binarized linear ----
    {
        unsigned bl[W], br[W];
#pragma unroll
        for (int w = 0; w < W; ++w) { bl[w] = g_b1l[o * W + w]; br[w] = g_b1r[o * W + w]; }
        const float b = bias1[o];

        float La[NPB], Lb[NPB], Ra[NPB], Rb[NPB];
#pragma unroll
        for (int ni = 0; ni < NPB; ++ni) { La[ni] = Lb[ni] = Ra[ni] = Rb[ni] = 0.f; }

#pragma unroll
        for (int w = 0; w < W; ++w) {
            unsigned l = bl[w], r = br[w];
#pragma unroll
            for (int k = 0; k < 32; k += 4) {
                int c4 = (w * 32 + k) >> 2;
                bool pl0 = (l >> k) & 1u, pl1 = (l >> (k + 1)) & 1u;
                bool pl2 = (l >> (k + 2)) & 1u, pl3 = (l >> (k + 3)) & 1u;
                bool pr0 = (r >> k) & 1u, pr1 = (r >> (k + 1)) & 1u;
                bool pr2 = (r >> (k + 2)) & 1u, pr3 = (r >> (k + 3)) & 1u;
#pragma unroll
                for (int ni = 0; ni < NPB; ++ni) {
                    float4 va = s_a4[ni][c4];
                    float4 vx = s_x4[ni][c4];
                    if (pl0) facc(La[ni], va.x);
                    if (pl1) facc(Lb[ni], va.y);
                    if (pl2) facc(La[ni], va.z);
                    if (pl3) facc(Lb[ni], va.w);
                    if (pr0) facc(Ra[ni], vx.x);
                    if (pr1) facc(Rb[ni], vx.y);
                    if (pr2) facc(Ra[ni], vx.z);
                    if (pr3) facc(Rb[ni], vx.w);
                }
            }
        }
#pragma unroll
        for (int ni = 0; ni < NPB; ++ni) {
            float res = (2.f * (La[ni] + Lb[ni]) - s_Ta[ni]) + b
                      + (2.f * (Ra[ni] + Rb[ni]) - s_Tx[ni]);
            ((float*)s_h4[ni])[o] = fmaxf(res, 0.f);
        }
    }
    __syncthreads();

    // per-node totals of h
    {
        int lane = o & 31, warp = o >> 5;
        const float* vh = (const float*)s_h4[warp];
        float t = 0.f;
#pragma unroll
        for (int f = lane; f < OUT; f += 32) t += vh[f];
#pragma unroll
        for (int off = 16; off; off >>= 1) t += __shfl_xor_sync(0xffffffffu, t, off);
        if (lane == 0) s_Th[warp] = t;
    }
    __syncthreads();

    // ---- layer-2 dual binarized transform (fused) ----
    {
        constexpr int W2 = 4;
        const int grp = o >> 6;
        const int oc  = o & 63;
        unsigned bl[W2], br[W2];
#pragma unroll
        for (int w = 0; w < W2; ++w) { bl[w] = g_b2l[oc * W2 + w]; br[w] = g_b2r[oc * W2 + w]; }
        const float b = bias2[oc];

        float La[2], Lb[2], Ra[2], Rb[2];
#pragma unroll
        for (int q = 0; q < 2; ++q) { La[q] = Lb[q] = Ra[q] = Rb[q] = 0.f; }

#pragma unroll
        for (int w = 0; w < W2; ++w) {
            unsigned l = bl[w], r = br[w];
#pragma unroll
            for (int k = 0; k < 32; k += 4) {
                int c4 = (w * 32 + k) >> 2;
                bool pl0 = (l >> k) & 1u, pl1 = (l >> (k + 1)) & 1u;
                bool pl2 = (l >> (k + 2)) & 1u, pl3 = (l >> (k + 3)) & 1u;
                bool pr0 = (r >> k) & 1u, pr1 = (r >> (k + 1)) & 1u;
                bool pr2 = (r >> (k + 2)) & 1u, pr3 = (r >> (k + 3)) & 1u;
#pragma unroll
                for (int q = 0; q < 2; ++q) {
                    float4 vh = s_h4[2 * grp + q][c4];
                    if (pl0) facc(La[q], vh.x);
                    if (pl1) facc(Lb[q], vh.y);
                    if (pl2) facc(La[q], vh.z);
                    if (pl3) facc(Lb[q], vh.w);
                    if (pr0) facc(Ra[q], vh.x);
                    if (pr1) facc(Rb[q], vh.y);
                    if (pr2) facc(Ra[q], vh.z);
                    if (pr3) facc(Rb[q], vh.w);
                }
            }
        }
#pragma unroll
        for (int q = 0; q < 2; ++q) {
            int ni = 2 * grp + q;
            float T = s_Th[ni];
            g_z[(size_t)(n0 + ni) * 64 + oc]  = 2.f * (La[q] + Lb[q]) - T;
            outp[(size_t)(n0 + ni) * 64 + oc] = 2.f * (Ra[q] + Rb[q]) - T + b;
        }
    }
}

// ---------------- layer 2b: float4 gather-aggregate of z ---------------------
// 16 nodes x 16 float4-chunks per 256-thread block
__global__ void __launch_bounds__(256) k_agg2(float* __restrict__ outp) {
    constexpr int F4 = 16, NPB = 16;
    __shared__ int s_start[NPB], s_deg[NPB];
    const int t  = threadIdx.x;
    const int n0 = blockIdx.x * NPB;
    if (t < NPB) {
        s_start[t] = g_row[n0 + t];
        s_deg[t]   = g_degi[n0 + t];
    }
    __syncthreads();
    int ni = t >> 4, c4 = t & 15;
    int st = s_start[ni], dg = s_deg[ni];
    const float4* z4 = (const float4*)g_z;
    float4 a0 = make_float4(0.f, 0.f, 0.f, 0.f);
    float4 a1 = a0, a2 = a0, a3 = a0;
    int j = 0;
    for (; j + 4 <= dg; j += 4) {
        int i0 = g_csr_src[st + j + 0];
        int i1 = g_csr_src[st + j + 1];
        int i2 = g_csr_src[st + j + 2];
        int i3 = g_csr_src[st + j + 3];
        float4 v0 = z4[(size_t)i0 * F4 + c4];
        float4 v1 = z4[(size_t)i1 * F4 + c4];
        float4 v2 = z4[(size_t)i2 * F4 + c4];
        float4 v3 = z4[(size_t)i3 * F4 + c4];
        a0.x += v0.x; a0.y += v0.y; a0.z += v0.z; a0.w += v0.w;
        a1.x += v1.x; a1.y += v1.y; a1.z += v1.z; a1.w += v1.w;
        a2.x += v2.x; a2.y += v2.y; a2.z += v2.z; a2.w += v2.w;
        a3.x += v3.x; a3.y += v3.y; a3.z += v3.z; a3.w += v3.w;
    }
    for (; j < dg; ++j) {
        float4 v = z4[(size_t)g_csr_src[st + j] * F4 + c4];
        a0.x += v.x; a0.y += v.y; a0.z += v.z; a0.w += v.w;
    }
    float inv = 1.f / fmaxf((float)dg, 1.f);
    float4* o4 = (float4*)outp;
    size_t oi = (size_t)(n0 + ni) * F4 + c4;
    float4 cur = o4[oi];
    cur.x += (a0.x + a1.x + a2.x + a3.x) * inv;
    cur.y += (a0.y + a1.y + a2.y + a3.y) * inv;
    cur.z += (a0.z + a1.z + a2.z + a3.z) * inv;
    cur.w += (a0.w + a1.w + a2.w + a3.w) * inv;
    o4[oi] = cur;
}

// ---------------- launch ----------------------------------------------------
extern "C" void kernel_launch(void* const* d_in, const int* in_sizes, int n_in,
                              void* d_out, int out_size) {
    const float* x   = (const float*)d_in[0];
    const void*  ei  = d_in[1];
    const float* w1l = (const float*)d_in[2];
    const float* b1  = (const float*)d_in[3];
    const float* w1r = (const float*)d_in[4];
    const float* w2l = (const float*)d_in[5];
    const float* b2  = (const float*)d_in[6];
    const float* w2r = (const float*)d_in[7];
    float*       out = (float*)d_out;

    k_init<<<NBLK, 256>>>((const int*)ei, w1l, w1r, w2l, w2r);
    k_conv<<<(E_EDGES / 2 + 255) / 256, 256>>>(ei);
    k_scanA<<<NBLK, 256>>>();
    k_scanB<<<1, 256>>>();
    k_scanC<<<NBLK, 256>>>();
    k_bucket<<<(E_EDGES + 255) / 256, 256>>>();
    k_sage1<<<N_NODES / 4, 128>>>(x, b1, b2, out);
    k_agg2<<<N_NODES / 16, 256>>>(out);
}